// round 11
// baseline (speedup 1.0000x reference)
#include <cuda_runtime.h>
#include <math_constants.h>

// Problem constants
#define B_ 32
#define L_ 8192
#define C_ 256
#define S_ 32                 // L-splits
#define CHUNK_ (L_ / S_)      // 256
#define MLP_ 4
#define NROWS_ (B_ * C_)      // 8192

// Partials, unpadded two-plane layout, row = b*C + c, slot s in 0..31:
//   plane A: float4 {mn0, mn1, mn2, mx0}   (4 MB)
//   plane B: float2 {mx1, mx2}             (2 MB)
__device__ float4 g_partA[(size_t)NROWS_ * S_];
__device__ float2 g_partB[(size_t)NROWS_ * S_];

// Merge running ascending triple with ascending (a0,a1,a2): keep 3 smallest. 7 ops.
__device__ __forceinline__ void merge_min(float a0, float a1, float a2,
                                          float& mn0, float& mn1, float& mn2) {
    float x0 = fminf(mn0, a0);
    float y0 = fmaxf(mn0, a0);
    float x1 = fminf(mn1, a1);
    float x2 = fminf(mn2, a2);
    float t  = fmaxf(x1, y0);
    mn0 = x0;
    mn1 = fminf(y0, x1);
    mn2 = fminf(x2, t);
}

// Merge running descending triple with descending (d0,d1,d2): keep 3 largest. 7 ops.
__device__ __forceinline__ void merge_max(float d0, float d1, float d2,
                                          float& mx0, float& mx1, float& mx2) {
    float x0 = fmaxf(mx0, d0);
    float y0 = fminf(mx0, d0);
    float x1 = fmaxf(mx1, d1);
    float x2 = fmaxf(mx2, d2);
    float t  = fminf(x1, y0);
    mx0 = x0;
    mx1 = fmaxf(y0, x1);
    mx2 = fmaxf(x2, t);
}

// Sort quad (10 ops) then merge both sides (7+7): 24 ops / 4 elements.
__device__ __forceinline__ void quad_update(float v0, float v1, float v2, float v3,
                                            float& mn0, float& mn1, float& mn2,
                                            float& mx0, float& mx1, float& mx2) {
    float a = fminf(v0, v1), b = fmaxf(v0, v1);
    float c = fminf(v2, v3), d = fmaxf(v2, v3);
    float a0 = fminf(a, c), t0 = fmaxf(a, c);
    float t1 = fminf(b, d), a3 = fmaxf(b, d);
    float a1 = fminf(t0, t1), a2 = fmaxf(t0, t1);
    merge_min(a0, a1, a2, mn0, mn1, mn2);   // a3 provably not among 3 smallest
    merge_max(a3, a2, a1, mx0, mx1, mx2);   // a0 provably not among 3 largest
}

// Pass 1: grid (S, B) = 1024 blocks x 256 threads = one full resident wave
// at 8 blocks/SM (64 warps/SM). Thread c scans CHUNK_ l-values, branchless.
// MLP=4 front-batched streaming loads (covers DRAM latency, minimizes
// cross-CTA L1tex-queue spread); __ldcs = evict-first for the zero-reuse input.
__global__ __launch_bounds__(C_, 8) void kmm_partial(const float* __restrict__ x) {
    const int c = threadIdx.x;
    const int s = blockIdx.x;
    const int b = blockIdx.y;

    const float* __restrict__ p =
        x + ((size_t)b * L_ + (size_t)s * CHUNK_) * C_ + c;

    float mx0 = -CUDART_INF_F, mx1 = -CUDART_INF_F, mx2 = -CUDART_INF_F;
    float mn0 =  CUDART_INF_F, mn1 =  CUDART_INF_F, mn2 =  CUDART_INF_F;

    for (int l = 0; l < CHUNK_; l += MLP_) {
        float v[MLP_];
#pragma unroll
        for (int j = 0; j < MLP_; j++)
            v[j] = __ldcs(p + (size_t)(l + j) * C_);
        quad_update(v[0], v[1], v[2], v[3], mn0, mn1, mn2, mx0, mx1, mx2);
    }

    const size_t slot = (size_t)(b * C_ + c) * S_ + s;
    g_partA[slot] = make_float4(mn0, mn1, mn2, mx0);
    g_partB[slot] = make_float2(mx1, mx2);
}

// Pass 2: 2 rows per warp, 16 lanes per row, 2 slots per lane.
// 8192 rows * 16 lanes = 131072 threads = 512 blocks x 256 (3.46 blocks/SM,
// much better wave balance than 256 blocks). Each lane: 4 independent loads
// in flight; local merge, then 4 butterfly rounds within the 16-lane group.
__global__ __launch_bounds__(256) void kmm_reduce(float* __restrict__ out) {
    const int gtid = blockIdx.x * 256 + threadIdx.x;
    const int lane = gtid & 31;
    const int s0   = lane & 15;                    // first slot
    const int row  = (gtid >> 5) * 2 + (lane >> 4);

    const size_t base = (size_t)row * S_;
    float4 a0 = __ldg(g_partA + base + s0);
    float4 a1 = __ldg(g_partA + base + s0 + 16);
    float2 b0 = __ldg(g_partB + base + s0);
    float2 b1 = __ldg(g_partB + base + s0 + 16);

    float mn0 = a0.x, mn1 = a0.y, mn2 = a0.z;
    float mx0 = a0.w, mx1 = b0.x, mx2 = b0.y;
    merge_min(a1.x, a1.y, a1.z, mn0, mn1, mn2);
    merge_max(a1.w, b1.x, b1.y, mx0, mx1, mx2);

#pragma unroll
    for (int off = 8; off > 0; off >>= 1) {
        float q0 = __shfl_xor_sync(0xffffffffu, mn0, off);
        float q1 = __shfl_xor_sync(0xffffffffu, mn1, off);
        float q2 = __shfl_xor_sync(0xffffffffu, mn2, off);
        float w0 = __shfl_xor_sync(0xffffffffu, mx0, off);
        float w1 = __shfl_xor_sync(0xffffffffu, mx1, off);
        float w2 = __shfl_xor_sync(0xffffffffu, mx2, off);
        merge_min(q0, q1, q2, mn0, mn1, mn2);
        merge_max(w0, w1, w2, mx0, mx1, mx2);
    }

    if (s0 == 0) {
        float* r = out + (size_t)row * 6;
        r[0] = mn0; r[1] = mn1; r[2] = mn2;
        r[3] = mx0; r[4] = mx1; r[5] = mx2;
    }
}

extern "C" void kernel_launch(void* const* d_in, const int* in_sizes, int n_in,
                              void* d_out, int out_size) {
    const float* x = (const float*)d_in[0];
    float* out = (float*)d_out;

    dim3 grid1(S_, B_);
    kmm_partial<<<grid1, C_>>>(x);

    // 8192 rows * 16 lanes = 131072 threads = 512 blocks x 256
    kmm_reduce<<<512, 256>>>(out);
}

// round 12
// speedup vs baseline: 1.0043x; 1.0043x over previous
#include <cuda_runtime.h>
#include <math_constants.h>

// Problem constants
#define B_ 32
#define L_ 8192
#define C_ 256
#define CG_ 16                // channels per block
#define NSG_ 32               // l-chunks per block (16 warps x 2 halves)
#define CHUNK_ (L_ / NSG_)    // 256 elements per thread
#define MLP_ 4
#define TPB_ 512

// Merge running ascending triple with ascending (a0,a1,a2): keep 3 smallest. 7 ops.
__device__ __forceinline__ void merge_min(float a0, float a1, float a2,
                                          float& mn0, float& mn1, float& mn2) {
    float x0 = fminf(mn0, a0);
    float y0 = fmaxf(mn0, a0);
    float x1 = fminf(mn1, a1);
    float x2 = fminf(mn2, a2);
    float t  = fmaxf(x1, y0);
    mn0 = x0;
    mn1 = fminf(y0, x1);
    mn2 = fminf(x2, t);
}

// Merge running descending triple with descending (d0,d1,d2): keep 3 largest. 7 ops.
__device__ __forceinline__ void merge_max(float d0, float d1, float d2,
                                          float& mx0, float& mx1, float& mx2) {
    float x0 = fmaxf(mx0, d0);
    float y0 = fminf(mx0, d0);
    float x1 = fmaxf(mx1, d1);
    float x2 = fmaxf(mx2, d2);
    float t  = fminf(x1, y0);
    mx0 = x0;
    mx1 = fmaxf(y0, x1);
    mx2 = fmaxf(x2, t);
}

// Sort quad (10 ops) then merge both sides (7+7): 24 ops / 4 elements.
__device__ __forceinline__ void quad_update(float v0, float v1, float v2, float v3,
                                            float& mn0, float& mn1, float& mn2,
                                            float& mx0, float& mx1, float& mx2) {
    float a = fminf(v0, v1), b = fmaxf(v0, v1);
    float c = fminf(v2, v3), d = fmaxf(v2, v3);
    float a0 = fminf(a, c), t0 = fmaxf(a, c);
    float t1 = fminf(b, d), a3 = fmaxf(b, d);
    float a1 = fminf(t0, t1), a2 = fmaxf(t0, t1);
    merge_min(a0, a1, a2, mn0, mn1, mn2);   // a3 provably not among 3 smallest
    merge_max(a3, a2, a1, mx0, mx1, mx2);   // a0 provably not among 3 largest
}

// Single kernel. Block = (cg, b): 16 channels x full L.
// 512 threads = 16 warps; thread t: c_local = t&15, sg = t>>4 (32 chunks).
// Warp = 16 c-lanes x 2 chunk-halves -> two 64B coalesced groups per load.
// Grid (16, 32) = 512 blocks, 4 blocks/SM = 64 warps/SM.
__global__ __launch_bounds__(TPB_, 4) void kmm_fused(const float* __restrict__ x,
                                                     float* __restrict__ out) {
    // warp-partials: [wp][c*6+k], row stride 97 words (conflict-free reads)
    __shared__ float sm[16 * 97];

    const int t    = threadIdx.x;
    const int cl   = t & 15;          // channel within group
    const int sg   = t >> 4;          // l-chunk index 0..31
    const int lane = t & 31;
    const int w    = t >> 5;          // warp id 0..15
    const int cg   = blockIdx.x;      // channel group 0..15
    const int b    = blockIdx.y;      // batch

    const float* __restrict__ p =
        x + ((size_t)b * L_ + (size_t)sg * CHUNK_) * C_ + (cg * CG_ + cl);

    float mx0 = -CUDART_INF_F, mx1 = -CUDART_INF_F, mx2 = -CUDART_INF_F;
    float mn0 =  CUDART_INF_F, mn1 =  CUDART_INF_F, mn2 =  CUDART_INF_F;

    for (int l = 0; l < CHUNK_; l += MLP_) {
        float v[MLP_];
#pragma unroll
        for (int j = 0; j < MLP_; j++)
            v[j] = __ldcs(p + (size_t)(l + j) * C_);
        quad_update(v[0], v[1], v[2], v[3], mn0, mn1, mn2, mx0, mx1, mx2);
    }

    // Intra-warp merge across the two chunk-halves (xor 16; same c both sides).
    {
        float q0 = __shfl_xor_sync(0xffffffffu, mn0, 16);
        float q1 = __shfl_xor_sync(0xffffffffu, mn1, 16);
        float q2 = __shfl_xor_sync(0xffffffffu, mn2, 16);
        float w0 = __shfl_xor_sync(0xffffffffu, mx0, 16);
        float w1 = __shfl_xor_sync(0xffffffffu, mx1, 16);
        float w2 = __shfl_xor_sync(0xffffffffu, mx2, 16);
        merge_min(q0, q1, q2, mn0, mn1, mn2);
        merge_max(w0, w1, w2, mx0, mx1, mx2);
    }

    // Lanes 0-15 hold the warp's merged triple for channel cl.
    if (lane < 16) {
        float* s = sm + w * 97 + cl * 6;
        s[0] = mn0; s[1] = mn1; s[2] = mn2;
        s[3] = mx0; s[4] = mx1; s[5] = mx2;
    }
    __syncthreads();

    // Final: warp w owns channel c_local = w. Lane reads warp-partial
    // (lane&15) for that channel (stride 97 -> conflict-free), then a
    // 4-round butterfly merges the 16 partials (data duplicated in both
    // half-warps, so xor 8/4/2/1 suffices).
    {
        const float* s = sm + (lane & 15) * 97 + w * 6;
        float n0 = s[0], n1 = s[1], n2 = s[2];
        float m0 = s[3], m1 = s[4], m2 = s[5];

#pragma unroll
        for (int off = 8; off > 0; off >>= 1) {
            float q0 = __shfl_xor_sync(0xffffffffu, n0, off);
            float q1 = __shfl_xor_sync(0xffffffffu, n1, off);
            float q2 = __shfl_xor_sync(0xffffffffu, n2, off);
            float w0 = __shfl_xor_sync(0xffffffffu, m0, off);
            float w1 = __shfl_xor_sync(0xffffffffu, m1, off);
            float w2 = __shfl_xor_sync(0xffffffffu, m2, off);
            merge_min(q0, q1, q2, n0, n1, n2);
            merge_max(w0, w1, w2, m0, m1, m2);
        }

        if (lane == 0) {
            const int row = b * C_ + cg * CG_ + w;
            float* r = out + (size_t)row * 6;
            r[0] = n0; r[1] = n1; r[2] = n2;
            r[3] = m0; r[4] = m1; r[5] = m2;
        }
    }
}

extern "C" void kernel_launch(void* const* d_in, const int* in_sizes, int n_in,
                              void* d_out, int out_size) {
    const float* x = (const float*)d_in[0];
    float* out = (float*)d_out;

    dim3 grid(C_ / CG_, B_);   // (16, 32) = 512 blocks
    kmm_fused<<<grid, TPB_>>>(x, out);
}